// round 12
// baseline (speedup 1.0000x reference)
#include <cuda_runtime.h>
#include <cuda_fp16.h>

// Problem constants (fixed by the reference)
#define N_NODES 100000
#define N_EDGES 50000
#define M_INC   1600000
#define D       64
#define DCH     8          // 16B chunks per fp16 row (8 lanes cover one row)
#define DC4     16         // float4 chunks per f32 row
#define MQ      (M_INC / 4)

// bit-cast helpers
__device__ __forceinline__ unsigned h2_as_u(__half2 h) {
    return *reinterpret_cast<unsigned*>(&h);
}
__device__ __forceinline__ __half2 u_as_h2(unsigned u) {
    return *reinterpret_cast<__half2*>(&u);
}

// ---------------------------------------------------------------------------
// Scratch (__device__ globals; zero-initialized at load).
// INVARIANT: g_Dn and g_Be are zero at every kernel_launch entry —
// k_recip restores g_Be, k_final restores g_Dn.
// ---------------------------------------------------------------------------
__device__ float  g_Dn[N_NODES];             // weighted node degree
__device__ float  g_Be[N_EDGES];             // edge cardinality (atomic target)
__device__ float  g_Ber[N_EDGES];            // 1/Be (read-only in stage2)
__device__ __half g_xh[(long)N_NODES * D];   // x in fp16
__device__ __half g_ef[(long)N_EDGES * D];   // raw edge feature sums, fp16
__device__ __half g_h [(long)N_NODES * D];   // unscaled node accumulator fp16

// ---------------------------------------------------------------------------
// K0 (prep): convert x->fp16, zero ef/h. No atomics.
// ---------------------------------------------------------------------------
__global__ void k_prep(const float* __restrict__ x) {
    long i = blockIdx.x * (long)blockDim.x + threadIdx.x;
    long stride = (long)gridDim.x * blockDim.x;

    const long XH8 = (long)N_NODES * D / 8;
    for (long j = i; j < XH8; j += stride) {
        float4 a = ((const float4*)x)[j * 2];
        float4 b = ((const float4*)x)[j * 2 + 1];
        uint4 u;
        u.x = h2_as_u(__floats2half2_rn(a.x, a.y));
        u.y = h2_as_u(__floats2half2_rn(a.z, a.w));
        u.z = h2_as_u(__floats2half2_rn(b.x, b.y));
        u.w = h2_as_u(__floats2half2_rn(b.z, b.w));
        ((uint4*)g_xh)[j] = u;
    }

    const long EF8 = (long)N_EDGES * D / 8;
    const long H8  = (long)N_NODES * D / 8;
    uint4 z = make_uint4(0u, 0u, 0u, 0u);
    for (long j = i; j < EF8; j += stride) ((uint4*)g_ef)[j] = z;
    for (long j = i; j < H8;  j += stride) ((uint4*)g_h)[j]  = z;
}

// ---------------------------------------------------------------------------
// K1: stage 1 — scatter ef[e] += xh[n] (raw fp16x2 vector REDG).
// thread t -> 16B chunk c = t&7; 4 incidences m = (t>>3) + q*MQ, q=0..3.
// 8 consecutive lanes cover one 128B row contiguously (coalesced); each
// warp-wide LDG.128 touches 4 contiguous rows. 4 independent chains/thread.
// Lane c==0 also counts edge cardinality (rides in the REDG shadow).
// ---------------------------------------------------------------------------
__global__ void k_stage1(const int* __restrict__ ni, const int* __restrict__ ei) {
    int t = blockIdx.x * blockDim.x + threadIdx.x;
    if (t >= MQ * DCH) return;
    int c = t & 7;
    int m = t >> 3;

    int n0 = __ldg(&ni[m]);
    int e0 = __ldg(&ei[m]);
    int n1 = __ldg(&ni[m + MQ]);
    int e1 = __ldg(&ei[m + MQ]);
    int n2 = __ldg(&ni[m + 2 * MQ]);
    int e2 = __ldg(&ei[m + 2 * MQ]);
    int n3 = __ldg(&ni[m + 3 * MQ]);
    int e3 = __ldg(&ei[m + 3 * MQ]);

    uint4 u0 = __ldg(&((const uint4*)g_xh)[(long)n0 * DCH + c]);
    uint4 u1 = __ldg(&((const uint4*)g_xh)[(long)n1 * DCH + c]);
    uint4 u2 = __ldg(&((const uint4*)g_xh)[(long)n2 * DCH + c]);
    uint4 u3 = __ldg(&((const uint4*)g_xh)[(long)n3 * DCH + c]);

    __half* d0 = &g_ef[(long)e0 * D + c * 8];
    __half* d1 = &g_ef[(long)e1 * D + c * 8];
    __half* d2 = &g_ef[(long)e2 * D + c * 8];
    __half* d3 = &g_ef[(long)e3 * D + c * 8];
    asm volatile("red.global.add.noftz.v4.f16x2 [%0], {%1,%2,%3,%4};"
                 :: "l"(d0), "r"(u0.x), "r"(u0.y), "r"(u0.z), "r"(u0.w) : "memory");
    asm volatile("red.global.add.noftz.v4.f16x2 [%0], {%1,%2,%3,%4};"
                 :: "l"(d1), "r"(u1.x), "r"(u1.y), "r"(u1.z), "r"(u1.w) : "memory");
    asm volatile("red.global.add.noftz.v4.f16x2 [%0], {%1,%2,%3,%4};"
                 :: "l"(d2), "r"(u2.x), "r"(u2.y), "r"(u2.z), "r"(u2.w) : "memory");
    asm volatile("red.global.add.noftz.v4.f16x2 [%0], {%1,%2,%3,%4};"
                 :: "l"(d3), "r"(u3.x), "r"(u3.y), "r"(u3.z), "r"(u3.w) : "memory");

    if (c == 0) {
        atomicAdd(&g_Be[e0], 1.0f);
        atomicAdd(&g_Be[e1], 1.0f);
        atomicAdd(&g_Be[e2], 1.0f);
        atomicAdd(&g_Be[e3], 1.0f);
    }
}

// ---------------------------------------------------------------------------
// K2: tiny recip — Ber[e] = 1/Be[e] (safe), restore Be[e] = 0.
// ---------------------------------------------------------------------------
__global__ void k_recip() {
    int e = blockIdx.x * blockDim.x + threadIdx.x;
    if (e >= N_EDGES) return;
    float b = g_Be[e];
    g_Ber[e] = (b > 0.f) ? (1.0f / b) : 0.f;
    g_Be[e] = 0.f;   // restore invariant for next call
}

// ---------------------------------------------------------------------------
// K3: stage 2 — h[n] += Ber[e] * ef[e] (scale folded into gather path).
// Same mapping as stage 1. Lane c==0 accumulates weighted Dn (consumed by
// k_final, which runs after); atomics ride in the REDG shadow.
// ---------------------------------------------------------------------------
__global__ void k_stage2(const int* __restrict__ ni, const int* __restrict__ ei,
                         const float* __restrict__ w) {
    int t = blockIdx.x * blockDim.x + threadIdx.x;
    if (t >= MQ * DCH) return;
    int c = t & 7;
    int m = t >> 3;

    int n0 = __ldg(&ni[m]);
    int e0 = __ldg(&ei[m]);
    int n1 = __ldg(&ni[m + MQ]);
    int e1 = __ldg(&ei[m + MQ]);
    int n2 = __ldg(&ni[m + 2 * MQ]);
    int e2 = __ldg(&ei[m + 2 * MQ]);
    int n3 = __ldg(&ni[m + 3 * MQ]);
    int e3 = __ldg(&ei[m + 3 * MQ]);

    __half2 r0 = __float2half2_rn(g_Ber[e0]);
    __half2 r1 = __float2half2_rn(g_Ber[e1]);
    __half2 r2 = __float2half2_rn(g_Ber[e2]);
    __half2 r3 = __float2half2_rn(g_Ber[e3]);

    uint4 u0 = __ldg(&((const uint4*)g_ef)[(long)e0 * DCH + c]);
    uint4 u1 = __ldg(&((const uint4*)g_ef)[(long)e1 * DCH + c]);
    uint4 u2 = __ldg(&((const uint4*)g_ef)[(long)e2 * DCH + c]);
    uint4 u3 = __ldg(&((const uint4*)g_ef)[(long)e3 * DCH + c]);

    u0.x = h2_as_u(__hmul2(u_as_h2(u0.x), r0));
    u0.y = h2_as_u(__hmul2(u_as_h2(u0.y), r0));
    u0.z = h2_as_u(__hmul2(u_as_h2(u0.z), r0));
    u0.w = h2_as_u(__hmul2(u_as_h2(u0.w), r0));
    u1.x = h2_as_u(__hmul2(u_as_h2(u1.x), r1));
    u1.y = h2_as_u(__hmul2(u_as_h2(u1.y), r1));
    u1.z = h2_as_u(__hmul2(u_as_h2(u1.z), r1));
    u1.w = h2_as_u(__hmul2(u_as_h2(u1.w), r1));
    u2.x = h2_as_u(__hmul2(u_as_h2(u2.x), r2));
    u2.y = h2_as_u(__hmul2(u_as_h2(u2.y), r2));
    u2.z = h2_as_u(__hmul2(u_as_h2(u2.z), r2));
    u2.w = h2_as_u(__hmul2(u_as_h2(u2.w), r2));
    u3.x = h2_as_u(__hmul2(u_as_h2(u3.x), r3));
    u3.y = h2_as_u(__hmul2(u_as_h2(u3.y), r3));
    u3.z = h2_as_u(__hmul2(u_as_h2(u3.z), r3));
    u3.w = h2_as_u(__hmul2(u_as_h2(u3.w), r3));

    __half* d0 = &g_h[(long)n0 * D + c * 8];
    __half* d1 = &g_h[(long)n1 * D + c * 8];
    __half* d2 = &g_h[(long)n2 * D + c * 8];
    __half* d3 = &g_h[(long)n3 * D + c * 8];
    asm volatile("red.global.add.noftz.v4.f16x2 [%0], {%1,%2,%3,%4};"
                 :: "l"(d0), "r"(u0.x), "r"(u0.y), "r"(u0.z), "r"(u0.w) : "memory");
    asm volatile("red.global.add.noftz.v4.f16x2 [%0], {%1,%2,%3,%4};"
                 :: "l"(d1), "r"(u1.x), "r"(u1.y), "r"(u1.z), "r"(u1.w) : "memory");
    asm volatile("red.global.add.noftz.v4.f16x2 [%0], {%1,%2,%3,%4};"
                 :: "l"(d2), "r"(u2.x), "r"(u2.y), "r"(u2.z), "r"(u2.w) : "memory");
    asm volatile("red.global.add.noftz.v4.f16x2 [%0], {%1,%2,%3,%4};"
                 :: "l"(d3), "r"(u3.x), "r"(u3.y), "r"(u3.z), "r"(u3.w) : "memory");

    if (c == 0) {
        float w0 = __ldg(&w[e0]);
        float w1 = __ldg(&w[e1]);
        float w2 = __ldg(&w[e2]);
        float w3 = __ldg(&w[e3]);
        atomicAdd(&g_Dn[n0], w0);
        atomicAdd(&g_Dn[n1], w1);
        atomicAdd(&g_Dn[n2], w2);
        atomicAdd(&g_Dn[n3], w3);
    }
}

// ---------------------------------------------------------------------------
// K4: final — out = 0.5*x + (0.5/Dn)*h, then restore Dn[node]=0.
// 16 lanes per node (one warp), lane-0 zero-store after all lanes' load.
// ---------------------------------------------------------------------------
__global__ void k_final(const float* __restrict__ x, float* __restrict__ out) {
    int t = blockIdx.x * blockDim.x + threadIdx.x;
    if (t >= N_NODES * DC4) return;
    int node = t >> 4;
    float dnv = g_Dn[node];
    float dn = (dnv > 0.f) ? (0.5f / dnv) : 0.f;

    float4 xv = ((const float4*)x)[t];
    uint2 hu = ((const uint2*)g_h)[t];
    float2 h01 = __half22float2(u_as_h2(hu.x));
    float2 h23 = __half22float2(u_as_h2(hu.y));

    float4 o;
    o.x = 0.5f * xv.x + dn * h01.x;
    o.y = 0.5f * xv.y + dn * h01.y;
    o.z = 0.5f * xv.z + dn * h23.x;
    o.w = 0.5f * xv.w + dn * h23.y;
    ((float4*)out)[t] = o;

    if ((t & 15) == 0) g_Dn[node] = 0.f;   // restore invariant for next call
}

// ---------------------------------------------------------------------------
extern "C" void kernel_launch(void* const* d_in, const int* in_sizes, int n_in,
                              void* d_out, int out_size) {
    const float* x  = (const float*)d_in[0];
    const int*   ni = (const int*)d_in[1];
    const int*   ei = (const int*)d_in[2];
    const float* w  = (const float*)d_in[3];
    float* out = (float*)d_out;

    const int T = 256;
    int stage_threads = MQ * DCH;                 // 3.2M threads

    k_prep<<<2048, T>>>(x);
    k_stage1<<<(stage_threads + T - 1) / T, T>>>(ni, ei);
    k_recip<<<(N_EDGES + T - 1) / T, T>>>();
    k_stage2<<<(stage_threads + T - 1) / T, T>>>(ni, ei, w);
    k_final<<<(N_NODES * DC4 + T - 1) / T, T>>>(x, out);
}

// round 13
// speedup vs baseline: 1.0156x; 1.0156x over previous
#include <cuda_runtime.h>
#include <cuda_fp16.h>

// Problem constants (fixed by the reference)
#define N_NODES 100000
#define N_EDGES 50000
#define M_INC   1600000
#define D       64
#define DCH     8          // 16B chunks per fp16 row (8 lanes cover one row)
#define DC4     16         // float4 chunks per f32 row
#define MH      (M_INC / 2)

// bit-cast helpers
__device__ __forceinline__ unsigned h2_as_u(__half2 h) {
    return *reinterpret_cast<unsigned*>(&h);
}
__device__ __forceinline__ __half2 u_as_h2(unsigned u) {
    return *reinterpret_cast<__half2*>(&u);
}

// ---------------------------------------------------------------------------
// Scratch (__device__ globals; zero-initialized at load).
// INVARIANT: g_Dn and g_Be are zero at every kernel_launch entry —
// k_recip restores g_Be, k_final restores g_Dn.
// ---------------------------------------------------------------------------
__device__ float  g_Dn[N_NODES];             // weighted node degree
__device__ float  g_Be[N_EDGES];             // edge cardinality (atomic target)
__device__ float  g_Ber[N_EDGES];            // 1/Be (read-only in stage2)
__device__ __half g_xh[(long)N_NODES * D];   // x in fp16
__device__ __half g_ef[(long)N_EDGES * D];   // raw edge feature sums, fp16
__device__ __half g_h [(long)N_NODES * D];   // unscaled node accumulator fp16

// ---------------------------------------------------------------------------
// K0 (prep): convert x->fp16, zero ef/h. No atomics.
// ---------------------------------------------------------------------------
__global__ void k_prep(const float* __restrict__ x) {
    long i = blockIdx.x * (long)blockDim.x + threadIdx.x;
    long stride = (long)gridDim.x * blockDim.x;

    const long XH8 = (long)N_NODES * D / 8;
    for (long j = i; j < XH8; j += stride) {
        float4 a = ((const float4*)x)[j * 2];
        float4 b = ((const float4*)x)[j * 2 + 1];
        uint4 u;
        u.x = h2_as_u(__floats2half2_rn(a.x, a.y));
        u.y = h2_as_u(__floats2half2_rn(a.z, a.w));
        u.z = h2_as_u(__floats2half2_rn(b.x, b.y));
        u.w = h2_as_u(__floats2half2_rn(b.z, b.w));
        ((uint4*)g_xh)[j] = u;
    }

    const long EF8 = (long)N_EDGES * D / 8;
    const long H8  = (long)N_NODES * D / 8;
    uint4 z = make_uint4(0u, 0u, 0u, 0u);
    for (long j = i; j < EF8; j += stride) ((uint4*)g_ef)[j] = z;
    for (long j = i; j < H8;  j += stride) ((uint4*)g_h)[j]  = z;
}

// ---------------------------------------------------------------------------
// K1: stage 1 — scatter ef[e] += xh[n] (raw fp16x2 vector REDG).
// thread t -> 16B chunk c = t&7, incidences m0 = t>>3 and m1 = m0 + M/2.
// 8 consecutive lanes cover one 128B row contiguously (coalesced).
// Side-work spread across lanes: c==0 counts Be, c==1 accumulates Dn.
// ---------------------------------------------------------------------------
__global__ void k_stage1(const int* __restrict__ ni, const int* __restrict__ ei,
                         const float* __restrict__ w) {
    int t = blockIdx.x * blockDim.x + threadIdx.x;
    if (t >= MH * DCH) return;
    int c  = t & 7;
    int m0 = t >> 3;
    int m1 = m0 + MH;

    int n0 = __ldg(&ni[m0]);
    int e0 = __ldg(&ei[m0]);
    int n1 = __ldg(&ni[m1]);
    int e1 = __ldg(&ei[m1]);

    uint4 u0 = __ldg(&((const uint4*)g_xh)[(long)n0 * DCH + c]);
    uint4 u1 = __ldg(&((const uint4*)g_xh)[(long)n1 * DCH + c]);

    __half* d0 = &g_ef[(long)e0 * D + c * 8];
    __half* d1 = &g_ef[(long)e1 * D + c * 8];
    asm volatile("red.global.add.noftz.v4.f16x2 [%0], {%1,%2,%3,%4};"
                 :: "l"(d0), "r"(u0.x), "r"(u0.y), "r"(u0.z), "r"(u0.w) : "memory");
    asm volatile("red.global.add.noftz.v4.f16x2 [%0], {%1,%2,%3,%4};"
                 :: "l"(d1), "r"(u1.x), "r"(u1.y), "r"(u1.z), "r"(u1.w) : "memory");

    if (c == 0) {
        atomicAdd(&g_Be[e0], 1.0f);
        atomicAdd(&g_Be[e1], 1.0f);
    } else if (c == 1) {
        float w0 = __ldg(&w[e0]);
        float w1 = __ldg(&w[e1]);
        atomicAdd(&g_Dn[n0], w0);
        atomicAdd(&g_Dn[n1], w1);
    }
}

// ---------------------------------------------------------------------------
// K2: tiny recip — Ber[e] = 1/Be[e] (safe), restore Be[e] = 0.
// One thread per edge; single reader/writer, race-free.
// ---------------------------------------------------------------------------
__global__ void k_recip() {
    int e = blockIdx.x * blockDim.x + threadIdx.x;
    if (e >= N_EDGES) return;
    float b = g_Be[e];
    g_Ber[e] = (b > 0.f) ? (1.0f / b) : 0.f;
    g_Be[e] = 0.f;   // restore invariant for next call
}

// ---------------------------------------------------------------------------
// K3: stage 2 — h[n] += Ber[e] * ef[e] (scale folded into the gather path).
// Same 8-lanes-per-row mapping as stage 1; Ber[e] broadcasts across the
// 8 lanes of an edge (L1 hit). Pure scatter, no side atomics.
// ---------------------------------------------------------------------------
__global__ void k_stage2(const int* __restrict__ ni, const int* __restrict__ ei) {
    int t = blockIdx.x * blockDim.x + threadIdx.x;
    if (t >= MH * DCH) return;
    int c  = t & 7;
    int m0 = t >> 3;
    int m1 = m0 + MH;

    int n0 = __ldg(&ni[m0]);
    int e0 = __ldg(&ei[m0]);
    int n1 = __ldg(&ni[m1]);
    int e1 = __ldg(&ei[m1]);

    __half2 r0 = __float2half2_rn(g_Ber[e0]);
    __half2 r1 = __float2half2_rn(g_Ber[e1]);

    uint4 u0 = __ldg(&((const uint4*)g_ef)[(long)e0 * DCH + c]);
    uint4 u1 = __ldg(&((const uint4*)g_ef)[(long)e1 * DCH + c]);

    u0.x = h2_as_u(__hmul2(u_as_h2(u0.x), r0));
    u0.y = h2_as_u(__hmul2(u_as_h2(u0.y), r0));
    u0.z = h2_as_u(__hmul2(u_as_h2(u0.z), r0));
    u0.w = h2_as_u(__hmul2(u_as_h2(u0.w), r0));
    u1.x = h2_as_u(__hmul2(u_as_h2(u1.x), r1));
    u1.y = h2_as_u(__hmul2(u_as_h2(u1.y), r1));
    u1.z = h2_as_u(__hmul2(u_as_h2(u1.z), r1));
    u1.w = h2_as_u(__hmul2(u_as_h2(u1.w), r1));

    __half* d0 = &g_h[(long)n0 * D + c * 8];
    __half* d1 = &g_h[(long)n1 * D + c * 8];
    asm volatile("red.global.add.noftz.v4.f16x2 [%0], {%1,%2,%3,%4};"
                 :: "l"(d0), "r"(u0.x), "r"(u0.y), "r"(u0.z), "r"(u0.w) : "memory");
    asm volatile("red.global.add.noftz.v4.f16x2 [%0], {%1,%2,%3,%4};"
                 :: "l"(d1), "r"(u1.x), "r"(u1.y), "r"(u1.z), "r"(u1.w) : "memory");
}

// ---------------------------------------------------------------------------
// K4: final — out = 0.5*x + (0.5/Dn)*h, then restore Dn[node]=0.
// 16 lanes per node (one warp), lane-0 zero-store after all lanes' load.
// ---------------------------------------------------------------------------
__global__ void k_final(const float* __restrict__ x, float* __restrict__ out) {
    int t = blockIdx.x * blockDim.x + threadIdx.x;
    if (t >= N_NODES * DC4) return;
    int node = t >> 4;
    float dnv = g_Dn[node];
    float dn = (dnv > 0.f) ? (0.5f / dnv) : 0.f;

    float4 xv = ((const float4*)x)[t];
    uint2 hu = ((const uint2*)g_h)[t];
    float2 h01 = __half22float2(u_as_h2(hu.x));
    float2 h23 = __half22float2(u_as_h2(hu.y));

    float4 o;
    o.x = 0.5f * xv.x + dn * h01.x;
    o.y = 0.5f * xv.y + dn * h01.y;
    o.z = 0.5f * xv.z + dn * h23.x;
    o.w = 0.5f * xv.w + dn * h23.y;
    ((float4*)out)[t] = o;

    if ((t & 15) == 0) g_Dn[node] = 0.f;   // restore invariant for next call
}

// ---------------------------------------------------------------------------
extern "C" void kernel_launch(void* const* d_in, const int* in_sizes, int n_in,
                              void* d_out, int out_size) {
    const float* x  = (const float*)d_in[0];
    const int*   ni = (const int*)d_in[1];
    const int*   ei = (const int*)d_in[2];
    const float* w  = (const float*)d_in[3];
    float* out = (float*)d_out;

    const int T = 256;
    int stage_threads = MH * DCH;                 // 6.4M threads

    k_prep<<<2048, T>>>(x);
    k_stage1<<<(stage_threads + T - 1) / T, T>>>(ni, ei, w);
    k_recip<<<(N_EDGES + T - 1) / T, T>>>();
    k_stage2<<<(stage_threads + T - 1) / T, T>>>(ni, ei);
    k_final<<<(N_NODES * DC4 + T - 1) / T, T>>>(x, out);
}

// round 14
// speedup vs baseline: 1.0173x; 1.0017x over previous
#include <cuda_runtime.h>
#include <cuda_fp16.h>

// Problem constants (fixed by the reference)
#define N_NODES 100000
#define N_EDGES 50000
#define M_INC   1600000
#define D       64
#define DCH     8          // 16B chunks per fp16 row (8 lanes cover one row)
#define DC4     16         // float4 chunks per f32 row
#define MH      (M_INC / 2)

// bit-cast helpers
__device__ __forceinline__ unsigned h2_as_u(__half2 h) {
    return *reinterpret_cast<unsigned*>(&h);
}
__device__ __forceinline__ __half2 u_as_h2(unsigned u) {
    return *reinterpret_cast<__half2*>(&u);
}

// ---------------------------------------------------------------------------
// Scratch (__device__ globals; allocation-free rule)
// ---------------------------------------------------------------------------
__device__ float  g_Dn[N_NODES];             // weighted node degree
__device__ float  g_Be[N_EDGES];             // edge cardinality
__device__ __half g_xh[(long)N_NODES * D];   // x in fp16
__device__ __half g_ef[(long)N_EDGES * D];   // raw edge feature sums, fp16
__device__ __half g_h [(long)N_NODES * D];   // unscaled node accumulator fp16

// ---------------------------------------------------------------------------
// K0 (prep): convert x->fp16, zero ef/h/Be/Dn. No atomics.
// ---------------------------------------------------------------------------
__global__ void k_prep(const float* __restrict__ x) {
    long i = blockIdx.x * (long)blockDim.x + threadIdx.x;
    long stride = (long)gridDim.x * blockDim.x;

    const long XH8 = (long)N_NODES * D / 8;
    for (long j = i; j < XH8; j += stride) {
        float4 a = ((const float4*)x)[j * 2];
        float4 b = ((const float4*)x)[j * 2 + 1];
        uint4 u;
        u.x = h2_as_u(__floats2half2_rn(a.x, a.y));
        u.y = h2_as_u(__floats2half2_rn(a.z, a.w));
        u.z = h2_as_u(__floats2half2_rn(b.x, b.y));
        u.w = h2_as_u(__floats2half2_rn(b.z, b.w));
        ((uint4*)g_xh)[j] = u;
    }

    const long EF8 = (long)N_EDGES * D / 8;
    const long H8  = (long)N_NODES * D / 8;
    uint4 z = make_uint4(0u, 0u, 0u, 0u);
    for (long j = i; j < EF8; j += stride) ((uint4*)g_ef)[j] = z;
    for (long j = i; j < H8;  j += stride) ((uint4*)g_h)[j]  = z;
    for (long j = i; j < N_NODES; j += stride) g_Dn[j] = 0.f;
    for (long j = i; j < N_EDGES; j += stride) g_Be[j] = 0.f;
}

// ---------------------------------------------------------------------------
// K1: stage 1 — scatter ef[e] += xh[n] (raw fp16x2 vector REDG).
// thread t -> 16B chunk c = t&7, incidences m0 = t>>3 and m1 = m0 + M/2.
// 8 consecutive lanes cover one 128B row contiguously (coalesced).
// Side-work spread across lanes: c==0 counts Be, c==1 accumulates Dn.
// ---------------------------------------------------------------------------
__global__ void k_stage1(const int* __restrict__ ni, const int* __restrict__ ei,
                         const float* __restrict__ w) {
    int t = blockIdx.x * blockDim.x + threadIdx.x;
    if (t >= MH * DCH) return;
    int c  = t & 7;
    int m0 = t >> 3;
    int m1 = m0 + MH;

    int n0 = __ldg(&ni[m0]);
    int e0 = __ldg(&ei[m0]);
    int n1 = __ldg(&ni[m1]);
    int e1 = __ldg(&ei[m1]);

    uint4 u0 = __ldg(&((const uint4*)g_xh)[(long)n0 * DCH + c]);
    uint4 u1 = __ldg(&((const uint4*)g_xh)[(long)n1 * DCH + c]);

    __half* d0 = &g_ef[(long)e0 * D + c * 8];
    __half* d1 = &g_ef[(long)e1 * D + c * 8];
    asm volatile("red.global.add.noftz.v4.f16x2 [%0], {%1,%2,%3,%4};"
                 :: "l"(d0), "r"(u0.x), "r"(u0.y), "r"(u0.z), "r"(u0.w) : "memory");
    asm volatile("red.global.add.noftz.v4.f16x2 [%0], {%1,%2,%3,%4};"
                 :: "l"(d1), "r"(u1.x), "r"(u1.y), "r"(u1.z), "r"(u1.w) : "memory");

    if (c == 0) {
        atomicAdd(&g_Be[e0], 1.0f);
        atomicAdd(&g_Be[e1], 1.0f);
    } else if (c == 1) {
        float w0 = __ldg(&w[e0]);
        float w1 = __ldg(&w[e1]);
        atomicAdd(&g_Dn[n0], w0);
        atomicAdd(&g_Dn[n1], w1);
    }
}

// ---------------------------------------------------------------------------
// K2: stage 2 — h[n] += (1/Be[e]) * ef[e], recip computed inline (MUFU is
// idle; Be[e] is an L1-broadcast load across the 8 lanes of an edge).
// Same 8-lanes-per-row mapping as stage 1. Pure scatter otherwise.
// ---------------------------------------------------------------------------
__global__ void k_stage2(const int* __restrict__ ni, const int* __restrict__ ei) {
    int t = blockIdx.x * blockDim.x + threadIdx.x;
    if (t >= MH * DCH) return;
    int c  = t & 7;
    int m0 = t >> 3;
    int m1 = m0 + MH;

    int n0 = __ldg(&ni[m0]);
    int e0 = __ldg(&ei[m0]);
    int n1 = __ldg(&ni[m1]);
    int e1 = __ldg(&ei[m1]);

    float b0 = g_Be[e0];
    float b1 = g_Be[e1];
    float br0 = (b0 > 0.f) ? __frcp_rn(b0) : 0.f;
    float br1 = (b1 > 0.f) ? __frcp_rn(b1) : 0.f;
    __half2 r0 = __float2half2_rn(br0);
    __half2 r1 = __float2half2_rn(br1);

    uint4 u0 = __ldg(&((const uint4*)g_ef)[(long)e0 * DCH + c]);
    uint4 u1 = __ldg(&((const uint4*)g_ef)[(long)e1 * DCH + c]);

    u0.x = h2_as_u(__hmul2(u_as_h2(u0.x), r0));
    u0.y = h2_as_u(__hmul2(u_as_h2(u0.y), r0));
    u0.z = h2_as_u(__hmul2(u_as_h2(u0.z), r0));
    u0.w = h2_as_u(__hmul2(u_as_h2(u0.w), r0));
    u1.x = h2_as_u(__hmul2(u_as_h2(u1.x), r1));
    u1.y = h2_as_u(__hmul2(u_as_h2(u1.y), r1));
    u1.z = h2_as_u(__hmul2(u_as_h2(u1.z), r1));
    u1.w = h2_as_u(__hmul2(u_as_h2(u1.w), r1));

    __half* d0 = &g_h[(long)n0 * D + c * 8];
    __half* d1 = &g_h[(long)n1 * D + c * 8];
    asm volatile("red.global.add.noftz.v4.f16x2 [%0], {%1,%2,%3,%4};"
                 :: "l"(d0), "r"(u0.x), "r"(u0.y), "r"(u0.z), "r"(u0.w) : "memory");
    asm volatile("red.global.add.noftz.v4.f16x2 [%0], {%1,%2,%3,%4};"
                 :: "l"(d1), "r"(u1.x), "r"(u1.y), "r"(u1.z), "r"(u1.w) : "memory");
}

// ---------------------------------------------------------------------------
// K3: final — out = 0.5*x + (0.5/Dn)*h (safe recip inline).
// ---------------------------------------------------------------------------
__global__ void k_final(const float* __restrict__ x, float* __restrict__ out) {
    int t = blockIdx.x * blockDim.x + threadIdx.x;
    if (t >= N_NODES * DC4) return;
    int node = t >> 4;
    float dnv = g_Dn[node];
    float dn = (dnv > 0.f) ? (0.5f / dnv) : 0.f;

    float4 xv = ((const float4*)x)[t];
    uint2 hu = ((const uint2*)g_h)[t];
    float2 h01 = __half22float2(u_as_h2(hu.x));
    float2 h23 = __half22float2(u_as_h2(hu.y));

    float4 o;
    o.x = 0.5f * xv.x + dn * h01.x;
    o.y = 0.5f * xv.y + dn * h01.y;
    o.z = 0.5f * xv.z + dn * h23.x;
    o.w = 0.5f * xv.w + dn * h23.y;
    ((float4*)out)[t] = o;
}

// ---------------------------------------------------------------------------
extern "C" void kernel_launch(void* const* d_in, const int* in_sizes, int n_in,
                              void* d_out, int out_size) {
    const float* x  = (const float*)d_in[0];
    const int*   ni = (const int*)d_in[1];
    const int*   ei = (const int*)d_in[2];
    const float* w  = (const float*)d_in[3];
    float* out = (float*)d_out;

    const int T = 256;
    int stage_threads = MH * DCH;                 // 6.4M threads

    k_prep<<<2048, T>>>(x);
    k_stage1<<<(stage_threads + T - 1) / T, T>>>(ni, ei, w);
    k_stage2<<<(stage_threads + T - 1) / T, T>>>(ni, ei);
    k_final<<<(N_NODES * DC4 + T - 1) / T, T>>>(x, out);
}

// round 15
// speedup vs baseline: 1.0340x; 1.0164x over previous
#include <cuda_runtime.h>
#include <cuda_fp16.h>

// Problem constants (fixed by the reference)
#define N_NODES 100000
#define N_EDGES 50000
#define M_INC   1600000
#define D       64
#define DCH     8          // 16B chunks per fp16 row (8 lanes cover one row)
#define DC4     16         // float4 chunks per f32 row
#define MH      (M_INC / 2)
#define FCH     (N_NODES * DC4)      // total float4 chunks in out (1.6M)
#define FCH2    (FCH / 2)

// bit-cast helpers
__device__ __forceinline__ unsigned h2_as_u(__half2 h) {
    return *reinterpret_cast<unsigned*>(&h);
}
__device__ __forceinline__ __half2 u_as_h2(unsigned u) {
    return *reinterpret_cast<__half2*>(&u);
}

// ---------------------------------------------------------------------------
// Scratch (__device__ globals; allocation-free rule)
// ---------------------------------------------------------------------------
__device__ float  g_Dn[N_NODES];             // weighted node degree
__device__ float  g_Be[N_EDGES];             // edge cardinality
__device__ __half g_xh[(long)N_NODES * D];   // x in fp16
__device__ __half g_ef[(long)N_EDGES * D];   // raw edge feature sums, fp16
__device__ __half g_h [(long)N_NODES * D];   // unscaled node accumulator fp16

// ---------------------------------------------------------------------------
// K0 (prep): convert x->fp16, zero ef/h/Be/Dn. No atomics.
// ---------------------------------------------------------------------------
__global__ void k_prep(const float* __restrict__ x) {
    long i = blockIdx.x * (long)blockDim.x + threadIdx.x;
    long stride = (long)gridDim.x * blockDim.x;

    const long XH8 = (long)N_NODES * D / 8;
    for (long j = i; j < XH8; j += stride) {
        float4 a = ((const float4*)x)[j * 2];
        float4 b = ((const float4*)x)[j * 2 + 1];
        uint4 u;
        u.x = h2_as_u(__floats2half2_rn(a.x, a.y));
        u.y = h2_as_u(__floats2half2_rn(a.z, a.w));
        u.z = h2_as_u(__floats2half2_rn(b.x, b.y));
        u.w = h2_as_u(__floats2half2_rn(b.z, b.w));
        ((uint4*)g_xh)[j] = u;
    }

    const long EF8 = (long)N_EDGES * D / 8;
    const long H8  = (long)N_NODES * D / 8;
    uint4 z = make_uint4(0u, 0u, 0u, 0u);
    for (long j = i; j < EF8; j += stride) ((uint4*)g_ef)[j] = z;
    for (long j = i; j < H8;  j += stride) ((uint4*)g_h)[j]  = z;
    for (long j = i; j < N_NODES; j += stride) g_Dn[j] = 0.f;
    for (long j = i; j < N_EDGES; j += stride) g_Be[j] = 0.f;
}

// ---------------------------------------------------------------------------
// K1: stage 1 — scatter ef[e] += xh[n] (raw fp16x2 vector REDG).
// thread t -> 16B chunk c = t&7, incidences m0 = t>>3 and m1 = m0 + M/2.
// Side-work spread across lanes: c==0 counts Be, c==1 accumulates Dn.
// ---------------------------------------------------------------------------
__global__ void k_stage1(const int* __restrict__ ni, const int* __restrict__ ei,
                         const float* __restrict__ w) {
    int t = blockIdx.x * blockDim.x + threadIdx.x;
    if (t >= MH * DCH) return;
    int c  = t & 7;
    int m0 = t >> 3;
    int m1 = m0 + MH;

    int n0 = __ldg(&ni[m0]);
    int e0 = __ldg(&ei[m0]);
    int n1 = __ldg(&ni[m1]);
    int e1 = __ldg(&ei[m1]);

    uint4 u0 = __ldg(&((const uint4*)g_xh)[(long)n0 * DCH + c]);
    uint4 u1 = __ldg(&((const uint4*)g_xh)[(long)n1 * DCH + c]);

    __half* d0 = &g_ef[(long)e0 * D + c * 8];
    __half* d1 = &g_ef[(long)e1 * D + c * 8];
    asm volatile("red.global.add.noftz.v4.f16x2 [%0], {%1,%2,%3,%4};"
                 :: "l"(d0), "r"(u0.x), "r"(u0.y), "r"(u0.z), "r"(u0.w) : "memory");
    asm volatile("red.global.add.noftz.v4.f16x2 [%0], {%1,%2,%3,%4};"
                 :: "l"(d1), "r"(u1.x), "r"(u1.y), "r"(u1.z), "r"(u1.w) : "memory");

    if (c == 0) {
        atomicAdd(&g_Be[e0], 1.0f);
        atomicAdd(&g_Be[e1], 1.0f);
    } else if (c == 1) {
        float w0 = __ldg(&w[e0]);
        float w1 = __ldg(&w[e1]);
        atomicAdd(&g_Dn[n0], w0);
        atomicAdd(&g_Dn[n1], w1);
    }
}

// ---------------------------------------------------------------------------
// K2: stage 2 — h[n] += (1/Be[e]) * ef[e], recip inline (MUFU idle;
// Be[e] is an L1-broadcast load across the 8 lanes of an edge).
// ---------------------------------------------------------------------------
__global__ void k_stage2(const int* __restrict__ ni, const int* __restrict__ ei) {
    int t = blockIdx.x * blockDim.x + threadIdx.x;
    if (t >= MH * DCH) return;
    int c  = t & 7;
    int m0 = t >> 3;
    int m1 = m0 + MH;

    int n0 = __ldg(&ni[m0]);
    int e0 = __ldg(&ei[m0]);
    int n1 = __ldg(&ni[m1]);
    int e1 = __ldg(&ei[m1]);

    float b0 = g_Be[e0];
    float b1 = g_Be[e1];
    float br0 = (b0 > 0.f) ? __frcp_rn(b0) : 0.f;
    float br1 = (b1 > 0.f) ? __frcp_rn(b1) : 0.f;
    __half2 r0 = __float2half2_rn(br0);
    __half2 r1 = __float2half2_rn(br1);

    uint4 u0 = __ldg(&((const uint4*)g_ef)[(long)e0 * DCH + c]);
    uint4 u1 = __ldg(&((const uint4*)g_ef)[(long)e1 * DCH + c]);

    u0.x = h2_as_u(__hmul2(u_as_h2(u0.x), r0));
    u0.y = h2_as_u(__hmul2(u_as_h2(u0.y), r0));
    u0.z = h2_as_u(__hmul2(u_as_h2(u0.z), r0));
    u0.w = h2_as_u(__hmul2(u_as_h2(u0.w), r0));
    u1.x = h2_as_u(__hmul2(u_as_h2(u1.x), r1));
    u1.y = h2_as_u(__hmul2(u_as_h2(u1.y), r1));
    u1.z = h2_as_u(__hmul2(u_as_h2(u1.z), r1));
    u1.w = h2_as_u(__hmul2(u_as_h2(u1.w), r1));

    __half* d0 = &g_h[(long)n0 * D + c * 8];
    __half* d1 = &g_h[(long)n1 * D + c * 8];
    asm volatile("red.global.add.noftz.v4.f16x2 [%0], {%1,%2,%3,%4};"
                 :: "l"(d0), "r"(u0.x), "r"(u0.y), "r"(u0.z), "r"(u0.w) : "memory");
    asm volatile("red.global.add.noftz.v4.f16x2 [%0], {%1,%2,%3,%4};"
                 :: "l"(d1), "r"(u1.x), "r"(u1.y), "r"(u1.z), "r"(u1.w) : "memory");
}

// ---------------------------------------------------------------------------
// K3: final — out = 0.5*xh + (0.5/Dn)*h, reading x from the fp16 copy
// (saves 12.8MB) and processing 2 independent chunks per thread (MLP).
// chunk = one float4 of out = one uint2 of xh = one uint2 of h.
// ---------------------------------------------------------------------------
__global__ void k_final(float* __restrict__ out) {
    int t = blockIdx.x * blockDim.x + threadIdx.x;
    if (t >= FCH2) return;

    int t0 = t;
    int t1 = t + FCH2;
    int node0 = t0 >> 4;
    int node1 = t1 >> 4;

    // issue all loads up front (independent chains)
    float dnv0 = g_Dn[node0];
    float dnv1 = g_Dn[node1];
    uint2 xu0 = ((const uint2*)g_xh)[t0];
    uint2 xu1 = ((const uint2*)g_xh)[t1];
    uint2 hu0 = ((const uint2*)g_h)[t0];
    uint2 hu1 = ((const uint2*)g_h)[t1];

    float dn0 = (dnv0 > 0.f) ? (0.5f / dnv0) : 0.f;
    float dn1 = (dnv1 > 0.f) ? (0.5f / dnv1) : 0.f;

    float2 x01 = __half22float2(u_as_h2(xu0.x));
    float2 x23 = __half22float2(u_as_h2(xu0.y));
    float2 h01 = __half22float2(u_as_h2(hu0.x));
    float2 h23 = __half22float2(u_as_h2(hu0.y));
    float4 o0;
    o0.x = 0.5f * x01.x + dn0 * h01.x;
    o0.y = 0.5f * x01.y + dn0 * h01.y;
    o0.z = 0.5f * x23.x + dn0 * h23.x;
    o0.w = 0.5f * x23.y + dn0 * h23.y;
    ((float4*)out)[t0] = o0;

    float2 y01 = __half22float2(u_as_h2(xu1.x));
    float2 y23 = __half22float2(u_as_h2(xu1.y));
    float2 g01 = __half22float2(u_as_h2(hu1.x));
    float2 g23 = __half22float2(u_as_h2(hu1.y));
    float4 o1;
    o1.x = 0.5f * y01.x + dn1 * g01.x;
    o1.y = 0.5f * y01.y + dn1 * g01.y;
    o1.z = 0.5f * y23.x + dn1 * g23.x;
    o1.w = 0.5f * y23.y + dn1 * g23.y;
    ((float4*)out)[t1] = o1;
}

// ---------------------------------------------------------------------------
extern "C" void kernel_launch(void* const* d_in, const int* in_sizes, int n_in,
                              void* d_out, int out_size) {
    const float* x  = (const float*)d_in[0];
    const int*   ni = (const int*)d_in[1];
    const int*   ei = (const int*)d_in[2];
    const float* w  = (const float*)d_in[3];
    float* out = (float*)d_out;

    const int T = 256;
    int stage_threads = MH * DCH;                 // 6.4M threads

    k_prep<<<2048, T>>>(x);
    k_stage1<<<(stage_threads + T - 1) / T, T>>>(ni, ei, w);
    k_stage2<<<(stage_threads + T - 1) / T, T>>>(ni, ei);
    k_final<<<(FCH2 + T - 1) / T, T>>>(out);
}